// round 14
// baseline (speedup 1.0000x reference)
#include <cuda_runtime.h>
#include <cuda_bf16.h>
#include <cstdint>
#include <cmath>

// Problem dims (fixed by the reference).
#define TT 512
#define BB 256
#define HH 512
#define G3 1536

// -------------------- device scratch (no cudaMalloc allowed) --------------------
// Fragment-major A operands: [t][mt(16)][kb(32)][lane(32)] -> uint4 (regs a0..a3).
__device__ uint4    g_Xfh[(size_t)TT * 16 * 32 * 32];   // 134 MB
__device__ uint4    g_Xfl[(size_t)TT * 16 * 32 * 32];   // 134 MB
__device__ uint4    g_Hfh[2 * 16 * 32 * 32];            // ping-pong h (hi)
__device__ uint4    g_Hfl[2 * 16 * 32 * 32];            // ping-pong h (lo)
__device__ uint16_t g_Wt_hi[(size_t)G3 * HH];           // input W, transposed [ncol][k]
__device__ uint16_t g_Wt_lo[(size_t)G3 * HH];
__device__ uint16_t g_Wht_hi[(size_t)G3 * HH];          // hidden W, transposed [ncol][k]
__device__ uint16_t g_Wht_lo[(size_t)G3 * HH];
__device__ float    g_bias[G3];                         // [b_ir | b_iz | b_in]
__device__ unsigned int g_bar4[4];                      // per-b-quarter barriers

// -------------------- helpers --------------------
__device__ __forceinline__ uint32_t smem_u32(const void* p) {
    uint32_t a;
    asm("{ .reg .u64 t; cvta.to.shared.u64 t, %1; cvt.u32.u64 %0, t; }" : "=r"(a) : "l"(p));
    return a;
}
__device__ __forceinline__ void ldm_x2(uint32_t* r, uint32_t addr) {
    asm volatile("ldmatrix.sync.aligned.m8n8.x2.shared.b16 {%0,%1}, [%2];"
                 : "=r"(r[0]), "=r"(r[1]) : "r"(addr));
}
__device__ __forceinline__ void mma16816(float* c, const uint32_t* a, const uint32_t* b) {
    asm volatile("mma.sync.aligned.m16n8k16.row.col.f32.bf16.bf16.f32 "
                 "{%0,%1,%2,%3}, {%4,%5,%6,%7}, {%8,%9}, {%0,%1,%2,%3};"
                 : "+f"(c[0]), "+f"(c[1]), "+f"(c[2]), "+f"(c[3])
                 : "r"(a[0]), "r"(a[1]), "r"(a[2]), "r"(a[3]), "r"(b[0]), "r"(b[1]));
}
__device__ __forceinline__ void split2(float x, uint16_t& h, uint16_t& l) {
    __nv_bfloat16 hb = __float2bfloat16_rn(x);
    __nv_bfloat16 lb = __float2bfloat16_rn(x - __bfloat162float(hb));
    h = __bfloat16_as_ushort(hb);
    l = __bfloat16_as_ushort(lb);
}
__device__ __forceinline__ float sigmoidf_(float x) { return 1.0f / (1.0f + expf(-x)); }

// ----------------------------------------------------------------------------
// Prep 1: split ins -> bf16 hi/lo in FRAGMENT-MAJOR layout (proven R13).
// ----------------------------------------------------------------------------
__global__ __launch_bounds__(256) void prep_x_kernel(const float* __restrict__ X) {
    size_t u = (size_t)blockIdx.x * 256 + threadIdx.x;
    if (u >= (size_t)TT * 16 * 32 * 32) return;
    const int l  = (int)(u & 31);
    const int kb = (int)((u >> 5) & 31);
    const int mt = (int)((u >> 10) & 15);
    const int t  = (int)(u >> 14);
    const int r0 = mt * 16 + (l >> 2);
    const int k0 = kb * 16 + (l & 3) * 2;
    const float* Xp = X + (size_t)t * BB * HH;
    float v[4][2];
    v[0][0] = Xp[(size_t)r0 * HH + k0];           v[0][1] = Xp[(size_t)r0 * HH + k0 + 1];
    v[1][0] = Xp[(size_t)(r0 + 8) * HH + k0];     v[1][1] = Xp[(size_t)(r0 + 8) * HH + k0 + 1];
    v[2][0] = Xp[(size_t)r0 * HH + k0 + 8];       v[2][1] = Xp[(size_t)r0 * HH + k0 + 9];
    v[3][0] = Xp[(size_t)(r0 + 8) * HH + k0 + 8]; v[3][1] = Xp[(size_t)(r0 + 8) * HH + k0 + 9];
    uint32_t hi[4], lo[4];
#pragma unroll
    for (int q = 0; q < 4; ++q) {
        uint16_t h0, l0, h1, l1;
        split2(v[q][0], h0, l0);
        split2(v[q][1], h1, l1);
        hi[q] = (uint32_t)h0 | ((uint32_t)h1 << 16);
        lo[q] = (uint32_t)l0 | ((uint32_t)l1 << 16);
    }
    g_Xfh[u] = make_uint4(hi[0], hi[1], hi[2], hi[3]);
    g_Xfl[u] = make_uint4(lo[0], lo[1], lo[2], lo[3]);
}

// ----------------------------------------------------------------------------
// Prep 2: transpose + split BOTH weight sets (unchanged, proven).
// ----------------------------------------------------------------------------
__global__ __launch_bounds__(256) void prep_w_kernel(
    const float* __restrict__ Wir, const float* __restrict__ Wiz, const float* __restrict__ Win,
    const float* __restrict__ Whr, const float* __restrict__ Whz, const float* __restrict__ Whn,
    const float* __restrict__ bir, const float* __restrict__ biz, const float* __restrict__ bin) {
    int u = blockIdx.x * 256 + threadIdx.x;
    if (u >= G3 * HH / 8) return;
    int ncol = u >> 6;
    int k0 = (u & 63) * 8;
    int gate = ncol >> 9, j = ncol & 511;
    const float* Wi = (gate == 0) ? Wir : (gate == 1) ? Wiz : Win;
    const float* Wh = (gate == 0) ? Whr : (gate == 1) ? Whz : Whn;
    uint16_t ih[8], il[8], hh[8], hl[8];
#pragma unroll
    for (int i = 0; i < 8; ++i) {
        split2(Wi[(size_t)(k0 + i) * HH + j], ih[i], il[i]);
        split2(Wh[(size_t)(k0 + i) * HH + j], hh[i], hl[i]);
    }
    size_t off = (size_t)ncol * HH + k0;
    *(uint4*)(g_Wt_hi + off)  = *(uint4*)ih;
    *(uint4*)(g_Wt_lo + off)  = *(uint4*)il;
    *(uint4*)(g_Wht_hi + off) = *(uint4*)hh;
    *(uint4*)(g_Wht_lo + off) = *(uint4*)hl;
    if ((u & 63) == 0) {
        const float* bias = (gate == 0) ? bir : (gate == 1) ? biz : bin;
        g_bias[ncol] = bias[j];
    }
}

// ----------------------------------------------------------------------------
// Prep 3: init_h -> fragment-major split buffers (parity 0); reset barriers.
// ----------------------------------------------------------------------------
__global__ __launch_bounds__(256) void prep_h_kernel(const float* __restrict__ H0) {
    int u = blockIdx.x * 256 + threadIdx.x;
    if (u < 4) g_bar4[u] = 0;
    if (u >= 16 * 32 * 32) return;
    const int l  = u & 31;
    const int kb = (u >> 5) & 31;
    const int mt = (u >> 10) & 15;
    const int r0 = mt * 16 + (l >> 2);
    const int k0 = kb * 16 + (l & 3) * 2;
    float v[4][2];
    v[0][0] = H0[(size_t)r0 * HH + k0];           v[0][1] = H0[(size_t)r0 * HH + k0 + 1];
    v[1][0] = H0[(size_t)(r0 + 8) * HH + k0];     v[1][1] = H0[(size_t)(r0 + 8) * HH + k0 + 1];
    v[2][0] = H0[(size_t)r0 * HH + k0 + 8];       v[2][1] = H0[(size_t)r0 * HH + k0 + 9];
    v[3][0] = H0[(size_t)(r0 + 8) * HH + k0 + 8]; v[3][1] = H0[(size_t)(r0 + 8) * HH + k0 + 9];
    uint32_t hi[4], lo[4];
#pragma unroll
    for (int q = 0; q < 4; ++q) {
        uint16_t h0, l0, h1, l1;
        split2(v[q][0], h0, l0);
        split2(v[q][1], h1, l1);
        hi[q] = (uint32_t)h0 | ((uint32_t)h1 << 16);
        lo[q] = (uint32_t)l0 | ((uint32_t)l1 << 16);
    }
    g_Hfh[u] = make_uint4(hi[0], hi[1], hi[2], hi[3]);
    g_Hfl[u] = make_uint4(lo[0], lo[1], lo[2], lo[3]);
}

// ----------------------------------------------------------------------------
// FUSED persistent GRU, fragment-fed. NEW warp layout 4m x 2k x 2f:
//  - each warp owns one f (8-column half) -> only 4 accumulators (r,z,xn,hn)
//  - 2-way k-reduction, ONE smem round (16KB), syncs/step 6 -> 4
//  - epilogue spread over 8 warps (4 h-values/thread, uint2 frag store)
// Grid (32 j x 4 b) = 128 CTAs, 512 thr = 16 warps.
// ----------------------------------------------------------------------------
#define SKB_WIH 0
#define SKB_WIL 49152
#define SKB_WHH 98304
#define SKB_WHL 147456
#define SKB_RED 196608
#define SKB_TOTAL 221184

__global__ __launch_bounds__(512, 1) void gru_persistent(
    const int* __restrict__ resets, const float* __restrict__ init_h,
    const float* __restrict__ bhn, float* __restrict__ out)
{
    extern __shared__ __align__(16) char sk_sm[];
    const uint32_t smb = smem_u32(sk_sm);
    float* red_buf = (float*)(sk_sm + SKB_RED);

    const int tid = threadIdx.x;
    const int w = tid >> 5, l = tid & 31;
    const int wm = w & 3;                 // m-warp 0..3
    const int wk = (w >> 2) & 1;          // k-half 0..1
    const int wf = w >> 3;                // f-half 0..1 (8-column group)
    const int j0 = blockIdx.x * 16;
    const int b0 = blockIdx.y * 64;
    const int g = l >> 2, tq = l & 3;
    const int mtg = blockIdx.y * 4 + wm;  // global 16-row tile index
    unsigned int* const my_bar = &g_bar4[blockIdx.y];

    // Load W slices once: 4 regions, blocked [k/16][48][16] (proven layout).
    for (int u = tid; u < 48 * 64; u += 512) {
        const int row = u >> 6, q = u & 63;
        const int gate = row >> 4;
        const int ncol = gate * 512 + j0 + (row & 15);
        const int k = q * 8;
        const uint32_t doff = (uint32_t)(((k >> 4) * 48 + row) * 32 + (k & 15) * 2);
        *(uint4*)(sk_sm + SKB_WIH + doff) = *(const uint4*)(g_Wt_hi  + (size_t)ncol * HH + k);
        *(uint4*)(sk_sm + SKB_WIL + doff) = *(const uint4*)(g_Wt_lo  + (size_t)ncol * HH + k);
        *(uint4*)(sk_sm + SKB_WHH + doff) = *(const uint4*)(g_Wht_hi + (size_t)ncol * HH + k);
        *(uint4*)(sk_sm + SKB_WHL + doff) = *(const uint4*)(g_Wht_lo + (size_t)ncol * HH + k);
    }
    __syncthreads();

    // B-fragment base offset for this warp's f-half; gate adds gate*512 bytes.
    const uint32_t woff_l = (uint32_t)((wf * 8 + (l & 7)) * 32 + ((l >> 3) & 1) * 16);

    // Epilogue constants + register h-carry (wk==0 warps, both f-halves).
    const int jj = j0 + wf * 8 + tq * 2;
    const float2 bir2 = *(const float2*)&g_bias[jj];
    const float2 biz2 = *(const float2*)&g_bias[512 + jj];
    const float2 bin2 = *(const float2*)&g_bias[1024 + jj];
    const float2 bhn2 = *(const float2*)&bhn[jj];
    float2 hc[2];
    if (wk == 0) {
#pragma unroll
        for (int rr = 0; rr < 2; ++rr)
            hc[rr] = *(const float2*)&init_h[(size_t)(b0 + wm * 16 + g + rr * 8) * HH + jj];
    }

    // Reset flags for this warp's two fragment rows (mask + epilogue).
    const int fr0 = b0 + wm * 16 + g;
    bool f0 = resets[fr0] != 0, f1 = resets[fr0 + 8] != 0;

    float c[4][4];   // 0=r, 1=z, 2=xn, 3=hn

    // x-phase: fills c[0..2] with x_t @ W_i partials (own k-half, own f).
#define X_PHASE(tx) {                                                              \
    _Pragma("unroll")                                                              \
    for (int i = 0; i < 3; ++i)                                                    \
        _Pragma("unroll")                                                          \
        for (int q = 0; q < 4; ++q) c[i][q] = 0.0f;                                \
    const size_t xb = (((size_t)(tx) * 16 + mtg) * 32 + wk * 16) * 32;             \
    uint4 fh = g_Xfh[xb + l];                                                      \
    uint4 fl = g_Xfl[xb + l];                                                      \
    _Pragma("unroll")                                                              \
    for (int ic = 0; ic < 16; ++ic) {                                              \
        uint4 nfh, nfl;                                                            \
        if (ic < 15) {                                                             \
            nfh = g_Xfh[xb + (ic + 1) * 32 + l];                                   \
            nfl = g_Xfl[xb + (ic + 1) * 32 + l];                                   \
        }                                                                          \
        const uint32_t afh[4] = {fh.x, fh.y, fh.z, fh.w};                          \
        const uint32_t afl[4] = {fl.x, fl.y, fl.z, fl.w};                          \
        const uint32_t wb = (uint32_t)((wk * 16 + ic) * 1536) + woff_l;            \
        _Pragma("unroll")                                                          \
        for (int gate = 0; gate < 3; ++gate) {                                     \
            uint32_t bfh[2], bfl[2];                                               \
            ldm_x2(bfh, smb + SKB_WIH + wb + (uint32_t)(gate * 512));              \
            ldm_x2(bfl, smb + SKB_WIL + wb + (uint32_t)(gate * 512));              \
            mma16816(c[gate], afh, bfh);                                           \
            mma16816(c[gate], afh, bfl);                                           \
            mma16816(c[gate], afl, bfh);                                           \
        }                                                                          \
        fh = nfh; fl = nfl;                                                        \
    } }

    X_PHASE(0);   // prologue

    for (int t = 0; t < TT; ++t) {
        const int par = t & 1;

        // ---- h-phase: h @ W_h into c[0..1] (+) and c[3] (fresh) ----
#pragma unroll
        for (int q = 0; q < 4; ++q) c[3][q] = 0.0f;
        {
            const uint32_t mm0 = f0 ? 0u : 0xFFFFFFFFu;
            const uint32_t mm1 = f1 ? 0u : 0xFFFFFFFFu;
            const size_t hb = (((size_t)par * 16 + mtg) * 32 + wk * 16) * 32;
            uint4 fh = g_Hfh[hb + l];
            uint4 fl = g_Hfl[hb + l];
#pragma unroll
            for (int ic = 0; ic < 16; ++ic) {
                uint4 nfh, nfl;
                if (ic < 15) {
                    nfh = g_Hfh[hb + (ic + 1) * 32 + l];
                    nfl = g_Hfl[hb + (ic + 1) * 32 + l];
                }
                const uint32_t afh[4] = {fh.x & mm0, fh.y & mm1, fh.z & mm0, fh.w & mm1};
                const uint32_t afl[4] = {fl.x & mm0, fl.y & mm1, fl.z & mm0, fl.w & mm1};
                const uint32_t wb = (uint32_t)((wk * 16 + ic) * 1536) + woff_l;
#pragma unroll
                for (int gate = 0; gate < 3; ++gate) {
                    uint32_t bfh[2], bfl[2];
                    ldm_x2(bfh, smb + SKB_WHH + wb + (uint32_t)(gate * 512));
                    ldm_x2(bfl, smb + SKB_WHL + wb + (uint32_t)(gate * 512));
                    float* acc = (gate < 2) ? c[gate] : c[3];
                    mma16816(acc, afh, bfh);
                    mma16816(acc, afh, bfl);
                    mma16816(acc, afl, bfh);
                }
                fh = nfh; fl = nfl;
            }
        }

        // ---- 2-way k reduction, one round (16KB in red region) ----
        if (wk == 1) {
            float* dst = red_buf + (wf * 4 + wm) * 32 + l;
#pragma unroll
            for (int i = 0; i < 4; ++i)
#pragma unroll
                for (int q = 0; q < 4; ++q)
                    dst[(i * 4 + q) * 256] = c[i][q];
        }
        __syncthreads();

        // ---- epilogue (wk==0, 8 warps): 2 rows x 2 cols per thread ----
        if (wk == 0) {
            const float* src = red_buf + (wf * 4 + wm) * 32 + l;
#pragma unroll
            for (int i = 0; i < 4; ++i)
#pragma unroll
                for (int q = 0; q < 4; ++q)
                    c[i][q] += src[(i * 4 + q) * 256];

            float* outt = out + (size_t)t * BB * HH;
            uint32_t ph[2], pl[2];
#pragma unroll
            for (int rr = 0; rr < 2; ++rr) {
                const int row = b0 + wm * 16 + g + rr * 8;
                const bool rz = (rr == 0) ? f0 : f1;
                float2 hp = hc[rr];
                if (rz) { hp.x = 0.0f; hp.y = 0.0f; }
                const float r0 = sigmoidf_(c[0][rr * 2 + 0] + bir2.x);
                const float r1 = sigmoidf_(c[0][rr * 2 + 1] + bir2.y);
                const float z0 = sigmoidf_(c[1][rr * 2 + 0] + biz2.x);
                const float z1 = sigmoidf_(c[1][rr * 2 + 1] + biz2.y);
                const float n0 = tanhf(c[2][rr * 2 + 0] + bin2.x + r0 * (c[3][rr * 2 + 0] + bhn2.x));
                const float n1 = tanhf(c[2][rr * 2 + 1] + bin2.y + r1 * (c[3][rr * 2 + 1] + bhn2.y));
                const float h0 = (1.0f - z0) * n0 + z0 * hp.x;
                const float h1 = (1.0f - z1) * n1 + z1 * hp.y;
                *(float2*)&outt[(size_t)row * HH + jj] = make_float2(h0, h1);
                hc[rr] = make_float2(h0, h1);
                uint16_t hh0, hl0, hh1, hl1;
                split2(h0, hh0, hl0);
                split2(h1, hh1, hl1);
                ph[rr] = (uint32_t)hh0 | ((uint32_t)hh1 << 16);
                pl[rr] = (uint32_t)hl0 | ((uint32_t)hl1 << 16);
            }
            // h fragment store: this thread owns components (wf*2 + rr) of the
            // uint4 a-frag at (parity^1, mtg, kb=blockIdx.x, lane l).
            const size_t widx = (((size_t)(par ^ 1) * 16 + mtg) * 32 + blockIdx.x) * 32 + l;
            ((uint2*)&g_Hfh[widx])[wf] = make_uint2(ph[0], ph[1]);
            ((uint2*)&g_Hfl[widx])[wf] = make_uint2(pl[0], pl[1]);
        }

        if (t + 1 < TT) {
            __syncthreads();   // all h stores done before the release-arrive
            if (tid == 0)
                asm volatile("red.release.gpu.add.u32 [%0], %1;" :: "l"(my_bar), "r"(1u) : "memory");

            // flags for t+1, then x-phase(t+1) — hides the barrier latency
            f0 = resets[(t + 1) * BB + fr0] != 0;
            f1 = resets[(t + 1) * BB + fr0 + 8] != 0;
            X_PHASE(t + 1);

            if (tid == 0) {
                const unsigned target = 32u * (unsigned)(t + 1);
                unsigned v;
                do {
                    asm volatile("ld.acquire.gpu.u32 %0, [%1];" : "=r"(v) : "l"(my_bar) : "memory");
                    if (v >= target) break;
                    __nanosleep(32);
                } while (true);
            }
            __syncthreads();
        }
    }
#undef X_PHASE
}

// ----------------------------------------------------------------------------
// Launch: 3 prep kernels + ONE fused fragment-fed persistent kernel.
// Graph-capturable (kernel launches only), allocation-free.
// ----------------------------------------------------------------------------
extern "C" void kernel_launch(void* const* d_in, const int* in_sizes, int n_in,
                              void* d_out, int out_size)
{
    const float* ins    = (const float*)d_in[0];
    const int*   resets = (const int*)d_in[1];
    const float* init_h = (const float*)d_in[2];
    const float* W_ir   = (const float*)d_in[3];
    const float* W_iz   = (const float*)d_in[4];
    const float* W_in   = (const float*)d_in[5];
    const float* b_ir   = (const float*)d_in[6];
    const float* b_iz   = (const float*)d_in[7];
    const float* b_in   = (const float*)d_in[8];
    const float* W_hr   = (const float*)d_in[9];
    const float* W_hz   = (const float*)d_in[10];
    const float* W_hn   = (const float*)d_in[11];
    const float* b_hn   = (const float*)d_in[12];
    float* out = (float*)d_out;

    cudaFuncSetAttribute(gru_persistent,
                         cudaFuncAttributeMaxDynamicSharedMemorySize, SKB_TOTAL);

    prep_x_kernel<<<(int)(((size_t)TT * 16 * 32 * 32 + 255) / 256), 256>>>(ins);
    prep_w_kernel<<<(G3 * HH / 8 + 255) / 256, 256>>>(W_ir, W_iz, W_in,
                                                      W_hr, W_hz, W_hn,
                                                      b_ir, b_iz, b_in);
    prep_h_kernel<<<(16 * 32 * 32 + 255) / 256, 256>>>(init_h);

    gru_persistent<<<dim3(32, 4), 512, SKB_TOTAL>>>(resets, init_h, b_hn, out);
}

// round 15
// speedup vs baseline: 1.1478x; 1.1478x over previous
#include <cuda_runtime.h>
#include <cuda_fp16.h>
#include <cstdint>
#include <cmath>

// Problem dims (fixed by the reference).
#define TT 512
#define BB 256
#define HH 512
#define G3 1536

// -------------------- device scratch (no cudaMalloc allowed) --------------------
// Fragment-major A operands (fp16): [t][mt(16)][kb(32)][lane(32)] -> uint4.
__device__ uint4    g_Xf[(size_t)TT * 16 * 32 * 32];   // 134 MB
__device__ uint4    g_Hf[2 * 16 * 32 * 32];            // ping-pong h frags
__device__ uint16_t g_Wt_hi[(size_t)G3 * HH];          // input W fp16 hi, transposed [ncol][k]
__device__ uint16_t g_Wt_lo[(size_t)G3 * HH];          // fp16 residual
__device__ uint16_t g_Wht_hi[(size_t)G3 * HH];         // hidden W fp16 hi
__device__ uint16_t g_Wht_lo[(size_t)G3 * HH];         // fp16 residual
__device__ float    g_bias[G3];                        // [b_ir | b_iz | b_in]
__device__ unsigned int g_bar4[4];                     // per-b-quarter barriers

// -------------------- helpers --------------------
__device__ __forceinline__ uint32_t smem_u32(const void* p) {
    uint32_t a;
    asm("{ .reg .u64 t; cvta.to.shared.u64 t, %1; cvt.u32.u64 %0, t; }" : "=r"(a) : "l"(p));
    return a;
}
__device__ __forceinline__ void ldm_x2(uint32_t* r, uint32_t addr) {
    asm volatile("ldmatrix.sync.aligned.m8n8.x2.shared.b16 {%0,%1}, [%2];"
                 : "=r"(r[0]), "=r"(r[1]) : "r"(addr));
}
// D(16x8,f32) += A(16x16 f16 row) * B(16x8 f16 col)
__device__ __forceinline__ void mma16816(float* c, const uint32_t* a, const uint32_t* b) {
    asm volatile("mma.sync.aligned.m16n8k16.row.col.f32.f16.f16.f32 "
                 "{%0,%1,%2,%3}, {%4,%5,%6,%7}, {%8,%9}, {%0,%1,%2,%3};"
                 : "+f"(c[0]), "+f"(c[1]), "+f"(c[2]), "+f"(c[3])
                 : "r"(a[0]), "r"(a[1]), "r"(a[2]), "r"(a[3]), "r"(b[0]), "r"(b[1]));
}
__device__ __forceinline__ uint16_t h16(float x) {
    return __half_as_ushort(__float2half_rn(x));
}
__device__ __forceinline__ void splitw(float x, uint16_t& h, uint16_t& l) {
    __half hb = __float2half_rn(x);
    __half lb = __float2half_rn(x - __half2float(hb));
    h = __half_as_ushort(hb);
    l = __half_as_ushort(lb);
}
__device__ __forceinline__ float sigmoidf_(float x) { return 1.0f / (1.0f + expf(-x)); }

// ----------------------------------------------------------------------------
// Prep 1: ins -> fp16 FRAGMENT-MAJOR layout (indexing proven in R13).
// Lane regs: a0=(r0,k0pair) a1=(r0+8,k0) a2=(r0,k0+8) a3=(r0+8,k0+8);
// r0=mt*16+(l>>2), k0=kb*16+(l&3)*2.
// ----------------------------------------------------------------------------
__global__ __launch_bounds__(256) void prep_x_kernel(const float* __restrict__ X) {
    size_t u = (size_t)blockIdx.x * 256 + threadIdx.x;
    if (u >= (size_t)TT * 16 * 32 * 32) return;
    const int l  = (int)(u & 31);
    const int kb = (int)((u >> 5) & 31);
    const int mt = (int)((u >> 10) & 15);
    const int t  = (int)(u >> 14);
    const int r0 = mt * 16 + (l >> 2);
    const int k0 = kb * 16 + (l & 3) * 2;
    const float* Xp = X + (size_t)t * BB * HH;
    uint32_t r[4];
    r[0] = (uint32_t)h16(Xp[(size_t)r0 * HH + k0])
         | ((uint32_t)h16(Xp[(size_t)r0 * HH + k0 + 1]) << 16);
    r[1] = (uint32_t)h16(Xp[(size_t)(r0 + 8) * HH + k0])
         | ((uint32_t)h16(Xp[(size_t)(r0 + 8) * HH + k0 + 1]) << 16);
    r[2] = (uint32_t)h16(Xp[(size_t)r0 * HH + k0 + 8])
         | ((uint32_t)h16(Xp[(size_t)r0 * HH + k0 + 9]) << 16);
    r[3] = (uint32_t)h16(Xp[(size_t)(r0 + 8) * HH + k0 + 8])
         | ((uint32_t)h16(Xp[(size_t)(r0 + 8) * HH + k0 + 9]) << 16);
    g_Xf[u] = make_uint4(r[0], r[1], r[2], r[3]);
}

// ----------------------------------------------------------------------------
// Prep 2: transpose + split-fp16 BOTH weight sets: Wt[ncol][k] = W_gate[k][j].
// ----------------------------------------------------------------------------
__global__ __launch_bounds__(256) void prep_w_kernel(
    const float* __restrict__ Wir, const float* __restrict__ Wiz, const float* __restrict__ Win,
    const float* __restrict__ Whr, const float* __restrict__ Whz, const float* __restrict__ Whn,
    const float* __restrict__ bir, const float* __restrict__ biz, const float* __restrict__ bin) {
    int u = blockIdx.x * 256 + threadIdx.x;
    if (u >= G3 * HH / 8) return;
    int ncol = u >> 6;
    int k0 = (u & 63) * 8;
    int gate = ncol >> 9, j = ncol & 511;
    const float* Wi = (gate == 0) ? Wir : (gate == 1) ? Wiz : Win;
    const float* Wh = (gate == 0) ? Whr : (gate == 1) ? Whz : Whn;
    uint16_t ih[8], il[8], hh[8], hl[8];
#pragma unroll
    for (int i = 0; i < 8; ++i) {
        splitw(Wi[(size_t)(k0 + i) * HH + j], ih[i], il[i]);
        splitw(Wh[(size_t)(k0 + i) * HH + j], hh[i], hl[i]);
    }
    size_t off = (size_t)ncol * HH + k0;
    *(uint4*)(g_Wt_hi + off)  = *(uint4*)ih;
    *(uint4*)(g_Wt_lo + off)  = *(uint4*)il;
    *(uint4*)(g_Wht_hi + off) = *(uint4*)hh;
    *(uint4*)(g_Wht_lo + off) = *(uint4*)hl;
    if ((u & 63) == 0) {
        const float* bias = (gate == 0) ? bir : (gate == 1) ? biz : bin;
        g_bias[ncol] = bias[j];
    }
}

// ----------------------------------------------------------------------------
// Prep 3: init_h -> fp16 fragment-major (parity 0); reset barriers.
// ----------------------------------------------------------------------------
__global__ __launch_bounds__(256) void prep_h_kernel(const float* __restrict__ H0) {
    int u = blockIdx.x * 256 + threadIdx.x;
    if (u < 4) g_bar4[u] = 0;
    if (u >= 16 * 32 * 32) return;
    const int l  = u & 31;
    const int kb = (u >> 5) & 31;
    const int mt = (u >> 10) & 15;
    const int r0 = mt * 16 + (l >> 2);
    const int k0 = kb * 16 + (l & 3) * 2;
    uint32_t r[4];
    r[0] = (uint32_t)h16(H0[(size_t)r0 * HH + k0])
         | ((uint32_t)h16(H0[(size_t)r0 * HH + k0 + 1]) << 16);
    r[1] = (uint32_t)h16(H0[(size_t)(r0 + 8) * HH + k0])
         | ((uint32_t)h16(H0[(size_t)(r0 + 8) * HH + k0 + 1]) << 16);
    r[2] = (uint32_t)h16(H0[(size_t)r0 * HH + k0 + 8])
         | ((uint32_t)h16(H0[(size_t)r0 * HH + k0 + 9]) << 16);
    r[3] = (uint32_t)h16(H0[(size_t)(r0 + 8) * HH + k0 + 8])
         | ((uint32_t)h16(H0[(size_t)(r0 + 8) * HH + k0 + 9]) << 16);
    g_Hf[u] = make_uint4(r[0], r[1], r[2], r[3]);
}

// ----------------------------------------------------------------------------
// FUSED persistent GRU, fragment-fed, R13 warp layout (4m x 4k — proven best),
// NEW 2-term precision: A fp16, W split-fp16 -> 2 MMAs per (ic, ni) not 3.
// Grid (32 j x 4 b) = 128 CTAs, 512 thr = 16 warps.
// Accumulators c[8][4]: 0..1=r, 2..3=z (x+h summed), 4..5=xn, 6..7=hn.
// ----------------------------------------------------------------------------
#define SKB_WIH 0
#define SKB_WIL 49152
#define SKB_WHH 98304
#define SKB_WHL 147456
#define SKB_RED 196608
#define SKB_TOTAL 221184

__global__ __launch_bounds__(512, 1) void gru_persistent(
    const int* __restrict__ resets, const float* __restrict__ init_h,
    const float* __restrict__ bhn, float* __restrict__ out)
{
    extern __shared__ __align__(16) char sk_sm[];
    const uint32_t smb = smem_u32(sk_sm);
    float* red_buf = (float*)(sk_sm + SKB_RED);

    const int tid = threadIdx.x;
    const int w = tid >> 5, l = tid & 31;
    const int wm = w & 3, wq = w >> 2;      // m-warp 0..3, k-quarter 0..3
    const int j0 = blockIdx.x * 16;
    const int b0 = blockIdx.y * 64;
    const int g = l >> 2, tq = l & 3;
    const int mtg = blockIdx.y * 4 + wm;    // global 16-row tile index
    unsigned int* const my_bar = &g_bar4[blockIdx.y];

    // Load W slices once: 4 regions, blocked [k/16][48][16] (proven layout).
    for (int u = tid; u < 48 * 64; u += 512) {
        const int row = u >> 6, q = u & 63;
        const int gate = row >> 4;
        const int ncol = gate * 512 + j0 + (row & 15);
        const int k = q * 8;
        const uint32_t doff = (uint32_t)(((k >> 4) * 48 + row) * 32 + (k & 15) * 2);
        *(uint4*)(sk_sm + SKB_WIH + doff) = *(const uint4*)(g_Wt_hi  + (size_t)ncol * HH + k);
        *(uint4*)(sk_sm + SKB_WIL + doff) = *(const uint4*)(g_Wt_lo  + (size_t)ncol * HH + k);
        *(uint4*)(sk_sm + SKB_WHH + doff) = *(const uint4*)(g_Wht_hi + (size_t)ncol * HH + k);
        *(uint4*)(sk_sm + SKB_WHL + doff) = *(const uint4*)(g_Wht_lo + (size_t)ncol * HH + k);
    }
    __syncthreads();

    const uint32_t woff_l = (uint32_t)((l & 7) * 32 + ((l >> 3) & 1) * 16);

    // Epilogue constants + register h-carry (wq==0 threads).
    float2 bir2[2], biz2[2], bin2[2], bhn2[2], hc[2][2];
#pragma unroll
    for (int f = 0; f < 2; ++f) {
        const int jj = j0 + f * 8 + tq * 2;
        bir2[f] = *(const float2*)&g_bias[jj];
        biz2[f] = *(const float2*)&g_bias[512 + jj];
        bin2[f] = *(const float2*)&g_bias[1024 + jj];
        bhn2[f] = *(const float2*)&bhn[jj];
    }
    if (wq == 0) {
#pragma unroll
        for (int rr = 0; rr < 2; ++rr) {
            const int row = b0 + wm * 16 + g + rr * 8;
#pragma unroll
            for (int f = 0; f < 2; ++f)
                hc[rr][f] = *(const float2*)&init_h[(size_t)row * HH + j0 + f * 8 + tq * 2];
        }
    }

    // Reset flags for this warp's two fragment rows (mask + epilogue).
    const int fr0 = b0 + wm * 16 + g;
    bool f0 = resets[fr0] != 0, f1 = resets[fr0 + 8] != 0;

    float c[8][4];

    // x-phase: fills c[0..5] with x_t @ W_i partials (own k-quarter). 2 terms.
#define X_PHASE(tx) {                                                              \
    _Pragma("unroll")                                                              \
    for (int i = 0; i < 6; ++i)                                                    \
        _Pragma("unroll")                                                          \
        for (int q = 0; q < 4; ++q) c[i][q] = 0.0f;                                \
    const size_t xb = ((size_t)(tx) * 16 + mtg) * 32;                              \
    uint4 fa = g_Xf[(xb + wq * 8) * 32 + l];                                       \
    _Pragma("unroll")                                                              \
    for (int ic = 0; ic < 8; ++ic) {                                               \
        uint4 nfa;                                                                 \
        if (ic < 7) nfa = g_Xf[(xb + wq * 8 + ic + 1) * 32 + l];                   \
        const uint32_t af[4] = {fa.x, fa.y, fa.z, fa.w};                           \
        const uint32_t wb = (uint32_t)((wq * 8 + ic) * 1536) + woff_l;             \
        _Pragma("unroll")                                                          \
        for (int ni = 0; ni < 6; ++ni) {                                           \
            uint32_t bfh[2], bfl[2];                                               \
            ldm_x2(bfh, smb + SKB_WIH + wb + (uint32_t)(ni * 256));                \
            ldm_x2(bfl, smb + SKB_WIL + wb + (uint32_t)(ni * 256));                \
            float* acc = (ni < 4) ? c[ni] : c[4 + (ni - 4)];                       \
            mma16816(acc, af, bfh);                                                \
            mma16816(acc, af, bfl);                                                \
        }                                                                          \
        fa = nfa;                                                                  \
    } }

    X_PHASE(0);   // prologue

    for (int t = 0; t < TT; ++t) {
        const int par = t & 1;

        // ---- h-phase: h @ W_h into c[0..3] (+) and c[6..7] (fresh), 2 terms ----
#pragma unroll
        for (int i = 6; i < 8; ++i)
#pragma unroll
            for (int q = 0; q < 4; ++q) c[i][q] = 0.0f;
        {
            const uint32_t mm0 = f0 ? 0u : 0xFFFFFFFFu;
            const uint32_t mm1 = f1 ? 0u : 0xFFFFFFFFu;
            const size_t hb = ((size_t)par * 16 + mtg) * 32;
            uint4 fa = g_Hf[(hb + wq * 8) * 32 + l];
#pragma unroll
            for (int ic = 0; ic < 8; ++ic) {
                uint4 nfa;
                if (ic < 7) nfa = g_Hf[(hb + wq * 8 + ic + 1) * 32 + l];
                const uint32_t af[4] = {fa.x & mm0, fa.y & mm1, fa.z & mm0, fa.w & mm1};
                const uint32_t wb = (uint32_t)((wq * 8 + ic) * 1536) + woff_l;
#pragma unroll
                for (int ni = 0; ni < 6; ++ni) {
                    uint32_t bfh[2], bfl[2];
                    ldm_x2(bfh, smb + SKB_WHH + wb + (uint32_t)(ni * 256));
                    ldm_x2(bfl, smb + SKB_WHL + wb + (uint32_t)(ni * 256));
                    float* acc = (ni < 4) ? c[ni] : c[6 + (ni - 4)];
                    mma16816(acc, af, bfh);
                    mma16816(acc, af, bfl);
                }
                fa = nfa;
            }
        }
        __syncthreads();

        // ---- 4-way k reduction, 2 rounds of 16 floats (24KB region) ----
#pragma unroll
        for (int rd = 0; rd < 2; ++rd) {
            if (wq != 0) {
                float* dst = red_buf + (wq - 1) * 128 + wm * 32 + l;
#pragma unroll
                for (int fi = 0; fi < 4; ++fi)
#pragma unroll
                    for (int q = 0; q < 4; ++q)
                        dst[(fi * 4 + q) * 384] = c[rd * 4 + fi][q];
            }
            __syncthreads();
            if (wq == 0) {
                const float* src = red_buf + wm * 32 + l;
#pragma unroll
                for (int fi = 0; fi < 4; ++fi)
#pragma unroll
                    for (int q = 0; q < 4; ++q) {
                        const float* s = src + (fi * 4 + q) * 384;
                        c[rd * 4 + fi][q] += s[0] + s[128] + s[256];
                    }
            }
            __syncthreads();
        }

        // ---- fused GRU epilogue (wq==0): out (fp32) + h as ONE frag store ----
        if (wq == 0) {
            float* outt = out + (size_t)t * BB * HH;
            uint4 vh;
            uint32_t* ph = (uint32_t*)&vh;
#pragma unroll
            for (int rr = 0; rr < 2; ++rr) {
                const int row = b0 + wm * 16 + g + rr * 8;
                const bool rz = (rr == 0) ? f0 : f1;
#pragma unroll
                for (int f = 0; f < 2; ++f) {
                    const int jj = j0 + f * 8 + tq * 2;
                    float2 hp = hc[rr][f];
                    if (rz) { hp.x = 0.0f; hp.y = 0.0f; }
                    const float r0 = sigmoidf_(c[f][rr * 2 + 0] + bir2[f].x);
                    const float r1 = sigmoidf_(c[f][rr * 2 + 1] + bir2[f].y);
                    const float z0 = sigmoidf_(c[2 + f][rr * 2 + 0] + biz2[f].x);
                    const float z1 = sigmoidf_(c[2 + f][rr * 2 + 1] + biz2[f].y);
                    const float n0 = tanhf(c[4 + f][rr * 2 + 0] + bin2[f].x
                                           + r0 * (c[6 + f][rr * 2 + 0] + bhn2[f].x));
                    const float n1 = tanhf(c[4 + f][rr * 2 + 1] + bin2[f].y
                                           + r1 * (c[6 + f][rr * 2 + 1] + bhn2[f].y));
                    const float h0 = (1.0f - z0) * n0 + z0 * hp.x;
                    const float h1 = (1.0f - z1) * n1 + z1 * hp.y;
                    *(float2*)&outt[(size_t)row * HH + jj] = make_float2(h0, h1);
                    hc[rr][f] = make_float2(h0, h1);
                    ph[f * 2 + rr] = (uint32_t)h16(h0) | ((uint32_t)h16(h1) << 16);
                }
            }
            const size_t widx = (((size_t)(par ^ 1) * 16 + mtg) * 32 + blockIdx.x) * 32 + l;
            g_Hf[widx] = vh;
        }

        if (t + 1 < TT) {
            __syncthreads();   // all h stores done before the release-arrive
            if (tid == 0)
                asm volatile("red.release.gpu.add.u32 [%0], %1;" :: "l"(my_bar), "r"(1u) : "memory");

            // flags for t+1, then x-phase(t+1) — hides the barrier latency
            f0 = resets[(t + 1) * BB + fr0] != 0;
            f1 = resets[(t + 1) * BB + fr0 + 8] != 0;
            X_PHASE(t + 1);

            if (tid == 0) {
                const unsigned target = 32u * (unsigned)(t + 1);
                unsigned v;
                do {
                    asm volatile("ld.acquire.gpu.u32 %0, [%1];" : "=r"(v) : "l"(my_bar) : "memory");
                    if (v >= target) break;
                    __nanosleep(32);
                } while (true);
            }
            __syncthreads();
        }
    }
#undef X_PHASE
}

// ----------------------------------------------------------------------------
// Launch: 3 prep kernels + ONE fused fragment-fed persistent kernel.
// Graph-capturable (kernel launches only), allocation-free.
// ----------------------------------------------------------------------------
extern "C" void kernel_launch(void* const* d_in, const int* in_sizes, int n_in,
                              void* d_out, int out_size)
{
    const float* ins    = (const float*)d_in[0];
    const int*   resets = (const int*)d_in[1];
    const float* init_h = (const float*)d_in[2];
    const float* W_ir   = (const float*)d_in[3];
    const float* W_iz   = (const float*)d_in[4];
    const float* W_in   = (const float*)d_in[5];
    const float* b_ir   = (const float*)d_in[6];
    const float* b_iz   = (const float*)d_in[7];
    const float* b_in   = (const float*)d_in[8];
    const float* W_hr   = (const float*)d_in[9];
    const float* W_hz   = (const float*)d_in[10];
    const float* W_hn   = (const float*)d_in[11];
    const float* b_hn   = (const float*)d_in[12];
    float* out = (float*)d_out;

    cudaFuncSetAttribute(gru_persistent,
                         cudaFuncAttributeMaxDynamicSharedMemorySize, SKB_TOTAL);

    prep_x_kernel<<<(int)(((size_t)TT * 16 * 32 * 32 + 255) / 256), 256>>>(ins);
    prep_w_kernel<<<(G3 * HH / 8 + 255) / 256, 256>>>(W_ir, W_iz, W_in,
                                                      W_hr, W_hz, W_hn,
                                                      b_ir, b_iz, b_in);
    prep_h_kernel<<<(16 * 32 * 32 + 255) / 256, 256>>>(init_h);

    gru_persistent<<<dim3(32, 4), 512, SKB_TOTAL>>>(resets, init_h, b_hn, out);
}

// round 16
// speedup vs baseline: 1.1763x; 1.0249x over previous
#include <cuda_runtime.h>
#include <cuda_fp16.h>
#include <cstdint>
#include <cmath>

// Problem dims (fixed by the reference).
#define TT 512
#define BB 256
#define HH 512
#define G3 1536

// -------------------- device scratch (no cudaMalloc allowed) --------------------
// Fragment-major A operands (fp16): [t][mt(16)][kb(32)][lane(32)] -> uint4.
__device__ uint4    g_Xf[(size_t)TT * 16 * 32 * 32];   // 134 MB
__device__ uint4    g_Hf[2 * 16 * 32 * 32];            // ping-pong h frags
__device__ uint16_t g_Wt_hi[(size_t)G3 * HH];          // input W fp16 hi, transposed [ncol][k]
__device__ uint16_t g_Wt_lo[(size_t)G3 * HH];          // fp16 residual
__device__ uint16_t g_Wht_hi[(size_t)G3 * HH];         // hidden W fp16 hi
__device__ uint16_t g_Wht_lo[(size_t)G3 * HH];         // fp16 residual
__device__ float    g_bias[G3];                        // [b_ir | b_iz | b_in]
__device__ unsigned int g_bar4[4];                     // per-b-quarter barriers (64 CTAs each)

// -------------------- helpers --------------------
__device__ __forceinline__ uint32_t smem_u32(const void* p) {
    uint32_t a;
    asm("{ .reg .u64 t; cvta.to.shared.u64 t, %1; cvt.u32.u64 %0, t; }" : "=r"(a) : "l"(p));
    return a;
}
__device__ __forceinline__ void ldm_x2(uint32_t* r, uint32_t addr) {
    asm volatile("ldmatrix.sync.aligned.m8n8.x2.shared.b16 {%0,%1}, [%2];"
                 : "=r"(r[0]), "=r"(r[1]) : "r"(addr));
}
// D(16x8,f32) += A(16x16 f16 row) * B(16x8 f16 col)
__device__ __forceinline__ void mma16816(float* c, const uint32_t* a, const uint32_t* b) {
    asm volatile("mma.sync.aligned.m16n8k16.row.col.f32.f16.f16.f32 "
                 "{%0,%1,%2,%3}, {%4,%5,%6,%7}, {%8,%9}, {%0,%1,%2,%3};"
                 : "+f"(c[0]), "+f"(c[1]), "+f"(c[2]), "+f"(c[3])
                 : "r"(a[0]), "r"(a[1]), "r"(a[2]), "r"(a[3]), "r"(b[0]), "r"(b[1]));
}
__device__ __forceinline__ uint16_t h16(float x) {
    return __half_as_ushort(__float2half_rn(x));
}
__device__ __forceinline__ void splitw(float x, uint16_t& h, uint16_t& l) {
    __half hb = __float2half_rn(x);
    __half lb = __float2half_rn(x - __half2float(hb));
    h = __half_as_ushort(hb);
    l = __half_as_ushort(lb);
}
__device__ __forceinline__ float sigmoidf_(float x) { return 1.0f / (1.0f + expf(-x)); }

// ----------------------------------------------------------------------------
// Prep 1: ins -> fp16 FRAGMENT-MAJOR layout (proven R13/R15 indexing).
// ----------------------------------------------------------------------------
__global__ __launch_bounds__(256) void prep_x_kernel(const float* __restrict__ X) {
    size_t u = (size_t)blockIdx.x * 256 + threadIdx.x;
    if (u >= (size_t)TT * 16 * 32 * 32) return;
    const int l  = (int)(u & 31);
    const int kb = (int)((u >> 5) & 31);
    const int mt = (int)((u >> 10) & 15);
    const int t  = (int)(u >> 14);
    const int r0 = mt * 16 + (l >> 2);
    const int k0 = kb * 16 + (l & 3) * 2;
    const float* Xp = X + (size_t)t * BB * HH;
    uint32_t r[4];
    r[0] = (uint32_t)h16(Xp[(size_t)r0 * HH + k0])
         | ((uint32_t)h16(Xp[(size_t)r0 * HH + k0 + 1]) << 16);
    r[1] = (uint32_t)h16(Xp[(size_t)(r0 + 8) * HH + k0])
         | ((uint32_t)h16(Xp[(size_t)(r0 + 8) * HH + k0 + 1]) << 16);
    r[2] = (uint32_t)h16(Xp[(size_t)r0 * HH + k0 + 8])
         | ((uint32_t)h16(Xp[(size_t)r0 * HH + k0 + 9]) << 16);
    r[3] = (uint32_t)h16(Xp[(size_t)(r0 + 8) * HH + k0 + 8])
         | ((uint32_t)h16(Xp[(size_t)(r0 + 8) * HH + k0 + 9]) << 16);
    g_Xf[u] = make_uint4(r[0], r[1], r[2], r[3]);
}

// ----------------------------------------------------------------------------
// Prep 2: transpose + split-fp16 BOTH weight sets (unchanged, proven).
// ----------------------------------------------------------------------------
__global__ __launch_bounds__(256) void prep_w_kernel(
    const float* __restrict__ Wir, const float* __restrict__ Wiz, const float* __restrict__ Win,
    const float* __restrict__ Whr, const float* __restrict__ Whz, const float* __restrict__ Whn,
    const float* __restrict__ bir, const float* __restrict__ biz, const float* __restrict__ bin) {
    int u = blockIdx.x * 256 + threadIdx.x;
    if (u >= G3 * HH / 8) return;
    int ncol = u >> 6;
    int k0 = (u & 63) * 8;
    int gate = ncol >> 9, j = ncol & 511;
    const float* Wi = (gate == 0) ? Wir : (gate == 1) ? Wiz : Win;
    const float* Wh = (gate == 0) ? Whr : (gate == 1) ? Whz : Whn;
    uint16_t ih[8], il[8], hh[8], hl[8];
#pragma unroll
    for (int i = 0; i < 8; ++i) {
        splitw(Wi[(size_t)(k0 + i) * HH + j], ih[i], il[i]);
        splitw(Wh[(size_t)(k0 + i) * HH + j], hh[i], hl[i]);
    }
    size_t off = (size_t)ncol * HH + k0;
    *(uint4*)(g_Wt_hi + off)  = *(uint4*)ih;
    *(uint4*)(g_Wt_lo + off)  = *(uint4*)il;
    *(uint4*)(g_Wht_hi + off) = *(uint4*)hh;
    *(uint4*)(g_Wht_lo + off) = *(uint4*)hl;
    if ((u & 63) == 0) {
        const float* bias = (gate == 0) ? bir : (gate == 1) ? biz : bin;
        g_bias[ncol] = bias[j];
    }
}

// ----------------------------------------------------------------------------
// Prep 3: init_h -> fp16 fragment-major (parity 0); reset barriers.
// ----------------------------------------------------------------------------
__global__ __launch_bounds__(256) void prep_h_kernel(const float* __restrict__ H0) {
    int u = blockIdx.x * 256 + threadIdx.x;
    if (u < 4) g_bar4[u] = 0;
    if (u >= 16 * 32 * 32) return;
    const int l  = u & 31;
    const int kb = (u >> 5) & 31;
    const int mt = (u >> 10) & 15;
    const int r0 = mt * 16 + (l >> 2);
    const int k0 = kb * 16 + (l & 3) * 2;
    uint32_t r[4];
    r[0] = (uint32_t)h16(H0[(size_t)r0 * HH + k0])
         | ((uint32_t)h16(H0[(size_t)r0 * HH + k0 + 1]) << 16);
    r[1] = (uint32_t)h16(H0[(size_t)(r0 + 8) * HH + k0])
         | ((uint32_t)h16(H0[(size_t)(r0 + 8) * HH + k0 + 1]) << 16);
    r[2] = (uint32_t)h16(H0[(size_t)r0 * HH + k0 + 8])
         | ((uint32_t)h16(H0[(size_t)r0 * HH + k0 + 9]) << 16);
    r[3] = (uint32_t)h16(H0[(size_t)(r0 + 8) * HH + k0 + 8])
         | ((uint32_t)h16(H0[(size_t)(r0 + 8) * HH + k0 + 9]) << 16);
    g_Hf[u] = make_uint4(r[0], r[1], r[2], r[3]);
}

// ----------------------------------------------------------------------------
// FUSED persistent GRU, fragment-fed, 2-term fp16 (proven R15 numerics).
// NEW: 2 CTAs/SM. Grid (64 j x 4 b) = 256 CTAs, 256 thr = 8 warps (4m x 2k).
// CTA tile: 64 rows x 8 j-cols -> 1 n-frag per gate -> c[4][4] (r,z,xn,hn).
// W smem 96KB + 8KB red = 104KB -> 2 co-resident CTAs/SM fill each other's
// reduction/epilogue/barrier bubbles. wk=1 warps run x-phase(t+1) during
// wk=0's epilogue; wk=0's x-phase hides the 64-CTA quarter barrier.
// ----------------------------------------------------------------------------
#define SKB_WIH 0
#define SKB_WIL 24576
#define SKB_WHH 49152
#define SKB_WHL 73728
#define SKB_RED 98304
#define SKB_TOTAL 106496

__global__ __launch_bounds__(256, 2) void gru_persistent(
    const int* __restrict__ resets, const float* __restrict__ init_h,
    const float* __restrict__ bhn, float* __restrict__ out)
{
    extern __shared__ __align__(16) char sk_sm[];
    const uint32_t smb = smem_u32(sk_sm);
    float* red_buf = (float*)(sk_sm + SKB_RED);

    const int tid = threadIdx.x;
    const int w = tid >> 5, l = tid & 31;
    const int wm = w & 3, wk = w >> 2;      // m-warp 0..3, k-half 0..1
    const int j0 = blockIdx.x * 8;          // 8 j-cols per gate
    const int kbj = blockIdx.x >> 1;        // h-frag k-block for these j-cols
    const int jpar = blockIdx.x & 1;        // low/high half of the 16-col block
    const int b0 = blockIdx.y * 64;
    const int g = l >> 2, tq = l & 3;
    const int mtg = blockIdx.y * 4 + wm;    // global 16-row tile index
    unsigned int* const my_bar = &g_bar4[blockIdx.y];

    // Load W slices once: 4 regions, blocked [k/16][24][16]; 24 ncols (3 gates x 8).
    for (int u = tid; u < 24 * 64; u += 256) {
        const int row = u >> 6, q = u & 63;
        const int gate = row >> 3;
        const int ncol = gate * 512 + j0 + (row & 7);
        const int k = q * 8;
        const uint32_t doff = (uint32_t)(((k >> 4) * 24 + row) * 32 + (k & 15) * 2);
        *(uint4*)(sk_sm + SKB_WIH + doff) = *(const uint4*)(g_Wt_hi  + (size_t)ncol * HH + k);
        *(uint4*)(sk_sm + SKB_WIL + doff) = *(const uint4*)(g_Wt_lo  + (size_t)ncol * HH + k);
        *(uint4*)(sk_sm + SKB_WHH + doff) = *(const uint4*)(g_Wht_hi + (size_t)ncol * HH + k);
        *(uint4*)(sk_sm + SKB_WHL + doff) = *(const uint4*)(g_Wht_lo + (size_t)ncol * HH + k);
    }
    __syncthreads();

    const uint32_t woff_l = (uint32_t)((l & 7) * 32 + ((l >> 3) & 1) * 16);

    // Epilogue constants + register h-carry (wk==0 threads).
    const int jj = j0 + tq * 2;
    const float2 bir2 = *(const float2*)&g_bias[jj];
    const float2 biz2 = *(const float2*)&g_bias[512 + jj];
    const float2 bin2 = *(const float2*)&g_bias[1024 + jj];
    const float2 bhn2 = *(const float2*)&bhn[jj];
    float2 hc[2];
    if (wk == 0) {
#pragma unroll
        for (int rr = 0; rr < 2; ++rr)
            hc[rr] = *(const float2*)&init_h[(size_t)(b0 + wm * 16 + g + rr * 8) * HH + jj];
    }

    // Reset flags for this warp's two fragment rows (mask + epilogue).
    const int fr0 = b0 + wm * 16 + g;
    bool f0 = resets[fr0] != 0, f1 = resets[fr0 + 8] != 0;

    float c[4][4];   // 0=r, 1=z, 2=xn, 3=hn

    // x-phase: fills c[0..2] with x_t @ W_i partials (own k-half). 2 terms.
#define X_PHASE(tx) {                                                              \
    _Pragma("unroll")                                                              \
    for (int i = 0; i < 3; ++i)                                                    \
        _Pragma("unroll")                                                          \
        for (int q = 0; q < 4; ++q) c[i][q] = 0.0f;                                \
    const size_t xb = (((size_t)(tx) * 16 + mtg) * 32 + wk * 16) * 32;             \
    uint4 fa = g_Xf[xb + l];                                                       \
    _Pragma("unroll")                                                              \
    for (int ic = 0; ic < 16; ++ic) {                                              \
        uint4 nfa;                                                                 \
        if (ic < 15) nfa = g_Xf[xb + (ic + 1) * 32 + l];                           \
        const uint32_t af[4] = {fa.x, fa.y, fa.z, fa.w};                           \
        const uint32_t wb = (uint32_t)((wk * 16 + ic) * 768) + woff_l;             \
        _Pragma("unroll")                                                          \
        for (int gate = 0; gate < 3; ++gate) {                                     \
            uint32_t bfh[2], bfl[2];                                               \
            ldm_x2(bfh, smb + SKB_WIH + wb + (uint32_t)(gate * 256));              \
            ldm_x2(bfl, smb + SKB_WIL + wb + (uint32_t)(gate * 256));              \
            mma16816(c[gate], af, bfh);                                            \
            mma16816(c[gate], af, bfl);                                            \
        }                                                                          \
        fa = nfa;                                                                  \
    } }

    X_PHASE(0);   // prologue

    for (int t = 0; t < TT; ++t) {
        const int par = t & 1;

        // ---- h-phase: h @ W_h into c[0..1] (+) and c[3] (fresh), 2 terms ----
#pragma unroll
        for (int q = 0; q < 4; ++q) c[3][q] = 0.0f;
        {
            const uint32_t mm0 = f0 ? 0u : 0xFFFFFFFFu;
            const uint32_t mm1 = f1 ? 0u : 0xFFFFFFFFu;
            const size_t hb = (((size_t)par * 16 + mtg) * 32 + wk * 16) * 32;
            uint4 fa = g_Hf[hb + l];
#pragma unroll
            for (int ic = 0; ic < 16; ++ic) {
                uint4 nfa;
                if (ic < 15) nfa = g_Hf[hb + (ic + 1) * 32 + l];
                const uint32_t af[4] = {fa.x & mm0, fa.y & mm1, fa.z & mm0, fa.w & mm1};
                const uint32_t wb = (uint32_t)((wk * 16 + ic) * 768) + woff_l;
#pragma unroll
                for (int gate = 0; gate < 3; ++gate) {
                    uint32_t bfh[2], bfl[2];
                    ldm_x2(bfh, smb + SKB_WHH + wb + (uint32_t)(gate * 256));
                    ldm_x2(bfl, smb + SKB_WHL + wb + (uint32_t)(gate * 256));
                    float* acc = (gate < 2) ? c[gate] : c[3];
                    mma16816(acc, af, bfh);
                    mma16816(acc, af, bfl);
                }
                fa = nfa;
            }
        }

        // ---- 2-way k reduction: wk=1 writes 16 floats (8KB), wk=0 adds ----
        if (wk == 1) {
            float* dst = red_buf + wm * 32 + l;
#pragma unroll
            for (int i = 0; i < 4; ++i)
#pragma unroll
                for (int q = 0; q < 4; ++q)
                    dst[(i * 4 + q) * 128] = c[i][q];
        }
        __syncthreads();

        if (wk == 1) {
            // x-phase(t+1) overlaps wk=0's epilogue (x independent of h).
            if (t + 1 < TT) {
                f0 = resets[(t + 1) * BB + fr0] != 0;
                f1 = resets[(t + 1) * BB + fr0 + 8] != 0;
                X_PHASE(t + 1);
            }
        } else {
            const float* src = red_buf + wm * 32 + l;
#pragma unroll
            for (int i = 0; i < 4; ++i)
#pragma unroll
                for (int q = 0; q < 4; ++q)
                    c[i][q] += src[(i * 4 + q) * 128];

            // ---- fused GRU epilogue: 2 rows x 2 cols; carry in registers ----
            float* outt = out + (size_t)t * BB * HH;
            uint32_t ph[2];
#pragma unroll
            for (int rr = 0; rr < 2; ++rr) {
                const int row = b0 + wm * 16 + g + rr * 8;
                const bool rz = (rr == 0) ? f0 : f1;
                float2 hp = hc[rr];
                if (rz) { hp.x = 0.0f; hp.y = 0.0f; }
                const float r0 = sigmoidf_(c[0][rr * 2 + 0] + bir2.x);
                const float r1 = sigmoidf_(c[0][rr * 2 + 1] + bir2.y);
                const float z0 = sigmoidf_(c[1][rr * 2 + 0] + biz2.x);
                const float z1 = sigmoidf_(c[1][rr * 2 + 1] + biz2.y);
                const float n0 = tanhf(c[2][rr * 2 + 0] + bin2.x + r0 * (c[3][rr * 2 + 0] + bhn2.x));
                const float n1 = tanhf(c[2][rr * 2 + 1] + bin2.y + r1 * (c[3][rr * 2 + 1] + bhn2.y));
                const float h0 = (1.0f - z0) * n0 + z0 * hp.x;
                const float h1 = (1.0f - z1) * n1 + z1 * hp.y;
                *(float2*)&outt[(size_t)row * HH + jj] = make_float2(h0, h1);
                hc[rr] = make_float2(h0, h1);
                ph[rr] = (uint32_t)h16(h0) | ((uint32_t)h16(h1) << 16);
            }
            // h fragment store: uint2 half (jpar) of the a-frag uint4 at
            // (parity^1, mtg, kbj, lane l). Components {0,1} or {2,3}.
            const size_t widx = (((size_t)(par ^ 1) * 16 + mtg) * 32 + kbj) * 32 + l;
            ((uint2*)&g_Hf[widx])[jpar] = make_uint2(ph[0], ph[1]);
        }

        if (t + 1 < TT) {
            __syncthreads();   // h stores done before the release-arrive
            if (tid == 0)
                asm volatile("red.release.gpu.add.u32 [%0], %1;" :: "l"(my_bar), "r"(1u) : "memory");

            if (wk == 0) {     // wk=1 already did its x-phase during the epilogue
                f0 = resets[(t + 1) * BB + fr0] != 0;
                f1 = resets[(t + 1) * BB + fr0 + 8] != 0;
                X_PHASE(t + 1);
            }

            if (tid == 0) {
                const unsigned target = 64u * (unsigned)(t + 1);
                unsigned v;
                do {
                    asm volatile("ld.acquire.gpu.u32 %0, [%1];" : "=r"(v) : "l"(my_bar) : "memory");
                    if (v >= target) break;
                    __nanosleep(32);
                } while (true);
            }
            __syncthreads();
        }
    }
#undef X_PHASE
}

// ----------------------------------------------------------------------------
// Launch: 3 prep kernels + ONE fused fragment-fed persistent kernel.
// Graph-capturable (kernel launches only), allocation-free.
// ----------------------------------------------------------------------------
extern "C" void kernel_launch(void* const* d_in, const int* in_sizes, int n_in,
                              void* d_out, int out_size)
{
    const float* ins    = (const float*)d_in[0];
    const int*   resets = (const int*)d_in[1];
    const float* init_h = (const float*)d_in[2];
    const float* W_ir   = (const float*)d_in[3];
    const float* W_iz   = (const float*)d_in[4];
    const float* W_in   = (const float*)d_in[5];
    const float* b_ir   = (const float*)d_in[6];
    const float* b_iz   = (const float*)d_in[7];
    const float* b_in   = (const float*)d_in[8];
    const float* W_hr   = (const float*)d_in[9];
    const float* W_hz   = (const float*)d_in[10];
    const float* W_hn   = (const float*)d_in[11];
    const float* b_hn   = (const float*)d_in[12];
    float* out = (float*)d_out;

    cudaFuncSetAttribute(gru_persistent,
                         cudaFuncAttributeMaxDynamicSharedMemorySize, SKB_TOTAL);

    prep_x_kernel<<<(int)(((size_t)TT * 16 * 32 * 32 + 255) / 256), 256>>>(ins);
    prep_w_kernel<<<(G3 * HH / 8 + 255) / 256, 256>>>(W_ir, W_iz, W_in,
                                                      W_hr, W_hz, W_hn,
                                                      b_ir, b_iz, b_in);
    prep_h_kernel<<<(16 * 32 * 32 + 255) / 256, 256>>>(init_h);

    gru_persistent<<<dim3(64, 4), 256, SKB_TOTAL>>>(resets, init_h, b_hn, out);
}

// round 17
// speedup vs baseline: 1.2279x; 1.0439x over previous
#include <cuda_runtime.h>
#include <cuda_fp16.h>
#include <cstdint>
#include <cmath>

// Problem dims (fixed by the reference).
#define TT 512
#define BB 256
#define HH 512
#define G3 1536

// -------------------- device scratch (no cudaMalloc allowed) --------------------
// Fragment-major A operands (fp16): [t][mt(16)][kb(32)][lane(32)] -> uint4.
__device__ uint4    g_Xf[(size_t)TT * 16 * 32 * 32];   // 134 MB
__device__ uint4    g_Hf[2 * 16 * 32 * 32];            // ping-pong h frags
__device__ uint16_t g_Wt_hi[(size_t)G3 * HH];          // input W fp16 hi, transposed [ncol][k]
__device__ uint16_t g_Wt_lo[(size_t)G3 * HH];          // fp16 residual
__device__ uint16_t g_Wht_hi[(size_t)G3 * HH];         // hidden W fp16 hi
__device__ uint16_t g_Wht_lo[(size_t)G3 * HH];         // fp16 residual
__device__ float    g_bias[G3];                        // [b_ir | b_iz | b_in]
__device__ unsigned int g_bar4[4];                     // per-b-quarter barriers (64 CTAs each)

// -------------------- helpers --------------------
__device__ __forceinline__ uint32_t smem_u32(const void* p) {
    uint32_t a;
    asm("{ .reg .u64 t; cvta.to.shared.u64 t, %1; cvt.u32.u64 %0, t; }" : "=r"(a) : "l"(p));
    return a;
}
__device__ __forceinline__ void ldm_x4(uint32_t* r, uint32_t addr) {
    asm volatile("ldmatrix.sync.aligned.m8n8.x4.shared.b16 {%0,%1,%2,%3}, [%4];"
                 : "=r"(r[0]), "=r"(r[1]), "=r"(r[2]), "=r"(r[3]) : "r"(addr));
}
// D(16x8,f32) += A(16x16 f16 row) * B(16x8 f16 col)
__device__ __forceinline__ void mma16816(float* c, const uint32_t* a, const uint32_t* b) {
    asm volatile("mma.sync.aligned.m16n8k16.row.col.f32.f16.f16.f32 "
                 "{%0,%1,%2,%3}, {%4,%5,%6,%7}, {%8,%9}, {%0,%1,%2,%3};"
                 : "+f"(c[0]), "+f"(c[1]), "+f"(c[2]), "+f"(c[3])
                 : "r"(a[0]), "r"(a[1]), "r"(a[2]), "r"(a[3]), "r"(b[0]), "r"(b[1]));
}
__device__ __forceinline__ uint16_t h16(float x) {
    return __half_as_ushort(__float2half_rn(x));
}
__device__ __forceinline__ void splitw(float x, uint16_t& h, uint16_t& l) {
    __half hb = __float2half_rn(x);
    __half lb = __float2half_rn(x - __half2float(hb));
    h = __half_as_ushort(hb);
    l = __half_as_ushort(lb);
}
__device__ __forceinline__ float sigmoidf_(float x) { return 1.0f / (1.0f + expf(-x)); }

// ----------------------------------------------------------------------------
// Prep 1: ins -> fp16 FRAGMENT-MAJOR layout (proven R13/R15 indexing).
// ----------------------------------------------------------------------------
__global__ __launch_bounds__(256) void prep_x_kernel(const float* __restrict__ X) {
    size_t u = (size_t)blockIdx.x * 256 + threadIdx.x;
    if (u >= (size_t)TT * 16 * 32 * 32) return;
    const int l  = (int)(u & 31);
    const int kb = (int)((u >> 5) & 31);
    const int mt = (int)((u >> 10) & 15);
    const int t  = (int)(u >> 14);
    const int r0 = mt * 16 + (l >> 2);
    const int k0 = kb * 16 + (l & 3) * 2;
    const float* Xp = X + (size_t)t * BB * HH;
    uint32_t r[4];
    r[0] = (uint32_t)h16(Xp[(size_t)r0 * HH + k0])
         | ((uint32_t)h16(Xp[(size_t)r0 * HH + k0 + 1]) << 16);
    r[1] = (uint32_t)h16(Xp[(size_t)(r0 + 8) * HH + k0])
         | ((uint32_t)h16(Xp[(size_t)(r0 + 8) * HH + k0 + 1]) << 16);
    r[2] = (uint32_t)h16(Xp[(size_t)r0 * HH + k0 + 8])
         | ((uint32_t)h16(Xp[(size_t)r0 * HH + k0 + 9]) << 16);
    r[3] = (uint32_t)h16(Xp[(size_t)(r0 + 8) * HH + k0 + 8])
         | ((uint32_t)h16(Xp[(size_t)(r0 + 8) * HH + k0 + 9]) << 16);
    g_Xf[u] = make_uint4(r[0], r[1], r[2], r[3]);
}

// ----------------------------------------------------------------------------
// Prep 2: transpose + split-fp16 BOTH weight sets (unchanged, proven).
// ----------------------------------------------------------------------------
__global__ __launch_bounds__(256) void prep_w_kernel(
    const float* __restrict__ Wir, const float* __restrict__ Wiz, const float* __restrict__ Win,
    const float* __restrict__ Whr, const float* __restrict__ Whz, const float* __restrict__ Whn,
    const float* __restrict__ bir, const float* __restrict__ biz, const float* __restrict__ bin) {
    int u = blockIdx.x * 256 + threadIdx.x;
    if (u >= G3 * HH / 8) return;
    int ncol = u >> 6;
    int k0 = (u & 63) * 8;
    int gate = ncol >> 9, j = ncol & 511;
    const float* Wi = (gate == 0) ? Wir : (gate == 1) ? Wiz : Win;
    const float* Wh = (gate == 0) ? Whr : (gate == 1) ? Whz : Whn;
    uint16_t ih[8], il[8], hh[8], hl[8];
#pragma unroll
    for (int i = 0; i < 8; ++i) {
        splitw(Wi[(size_t)(k0 + i) * HH + j], ih[i], il[i]);
        splitw(Wh[(size_t)(k0 + i) * HH + j], hh[i], hl[i]);
    }
    size_t off = (size_t)ncol * HH + k0;
    *(uint4*)(g_Wt_hi + off)  = *(uint4*)ih;
    *(uint4*)(g_Wt_lo + off)  = *(uint4*)il;
    *(uint4*)(g_Wht_hi + off) = *(uint4*)hh;
    *(uint4*)(g_Wht_lo + off) = *(uint4*)hl;
    if ((u & 63) == 0) {
        const float* bias = (gate == 0) ? bir : (gate == 1) ? biz : bin;
        g_bias[ncol] = bias[j];
    }
}

// ----------------------------------------------------------------------------
// Prep 3: init_h -> fp16 fragment-major (parity 0); reset barriers.
// ----------------------------------------------------------------------------
__global__ __launch_bounds__(256) void prep_h_kernel(const float* __restrict__ H0) {
    int u = blockIdx.x * 256 + threadIdx.x;
    if (u < 4) g_bar4[u] = 0;
    if (u >= 16 * 32 * 32) return;
    const int l  = u & 31;
    const int kb = (u >> 5) & 31;
    const int mt = (u >> 10) & 15;
    const int r0 = mt * 16 + (l >> 2);
    const int k0 = kb * 16 + (l & 3) * 2;
    uint32_t r[4];
    r[0] = (uint32_t)h16(H0[(size_t)r0 * HH + k0])
         | ((uint32_t)h16(H0[(size_t)r0 * HH + k0 + 1]) << 16);
    r[1] = (uint32_t)h16(H0[(size_t)(r0 + 8) * HH + k0])
         | ((uint32_t)h16(H0[(size_t)(r0 + 8) * HH + k0 + 1]) << 16);
    r[2] = (uint32_t)h16(H0[(size_t)r0 * HH + k0 + 8])
         | ((uint32_t)h16(H0[(size_t)r0 * HH + k0 + 9]) << 16);
    r[3] = (uint32_t)h16(H0[(size_t)(r0 + 8) * HH + k0 + 8])
         | ((uint32_t)h16(H0[(size_t)(r0 + 8) * HH + k0 + 9]) << 16);
    g_Hf[u] = make_uint4(r[0], r[1], r[2], r[3]);
}

// ----------------------------------------------------------------------------
// FUSED persistent GRU (R16 structure, proven). NEW this round:
//  - W hi/lo MERGED per set: ic-block = 48 rows (gate*16 + hl*8 + j) x 16 k
//    -> ONE ldm_x4 per gate yields {hi-frag, lo-frag}: 3 ldm_x4/ic (was 6 x2)
//  - A-fragment prefetch depth 2 (two LDG.128 in flight covers L2 latency)
// Grid (64 j x 4 b) = 256 CTAs, 256 thr = 8 warps (4m x 2k), 2 CTAs/SM.
// ----------------------------------------------------------------------------
#define SKB_WI 0
#define SKB_WH 49152
#define SKB_RED 98304
#define SKB_TOTAL 106496

__global__ __launch_bounds__(256, 2) void gru_persistent(
    const int* __restrict__ resets, const float* __restrict__ init_h,
    const float* __restrict__ bhn, float* __restrict__ out)
{
    extern __shared__ __align__(16) char sk_sm[];
    const uint32_t smb = smem_u32(sk_sm);
    float* red_buf = (float*)(sk_sm + SKB_RED);

    const int tid = threadIdx.x;
    const int w = tid >> 5, l = tid & 31;
    const int wm = w & 3, wk = w >> 2;      // m-warp 0..3, k-half 0..1
    const int j0 = blockIdx.x * 8;          // 8 j-cols per gate
    const int kbj = blockIdx.x >> 1;        // h-frag k-block for these j-cols
    const int jpar = blockIdx.x & 1;        // low/high half of the 16-col block
    const int b0 = blockIdx.y * 64;
    const int g = l >> 2, tq = l & 3;
    const int mtg = blockIdx.y * 4 + wm;    // global 16-row tile index
    unsigned int* const my_bar = &g_bar4[blockIdx.y];

    // Load W once, MERGED layout: [k/16][48 rows][16 k-halves], row = gate*16+hl*8+jj.
    for (int u = tid; u < 48 * 64; u += 256) {
        const int row = u >> 6, q = u & 63;
        const int gate = row >> 4;
        const int hl = (row >> 3) & 1;
        const int jj = row & 7;
        const int ncol = gate * 512 + j0 + jj;
        const int k = q * 8;
        const uint32_t doff = (uint32_t)(((k >> 4) * 48 + row) * 32 + (k & 15) * 2);
        const uint16_t* si = hl ? g_Wt_lo : g_Wt_hi;
        const uint16_t* sh = hl ? g_Wht_lo : g_Wht_hi;
        *(uint4*)(sk_sm + SKB_WI + doff) = *(const uint4*)(si + (size_t)ncol * HH + k);
        *(uint4*)(sk_sm + SKB_WH + doff) = *(const uint4*)(sh + (size_t)ncol * HH + k);
    }
    __syncthreads();

    // ldm_x4 lane offset: lanes 0-15 -> hi rows (+k-half), lanes 16-31 -> lo rows.
    const uint32_t woff_l = (uint32_t)(((l >> 4) & 1) * 256 + (l & 7) * 32 + ((l >> 3) & 1) * 16);

    // Epilogue constants + register h-carry (wk==0 threads).
    const int jj = j0 + tq * 2;
    const float2 bir2 = *(const float2*)&g_bias[jj];
    const float2 biz2 = *(const float2*)&g_bias[512 + jj];
    const float2 bin2 = *(const float2*)&g_bias[1024 + jj];
    const float2 bhn2 = *(const float2*)&bhn[jj];
    float2 hc[2];
    if (wk == 0) {
#pragma unroll
        for (int rr = 0; rr < 2; ++rr)
            hc[rr] = *(const float2*)&init_h[(size_t)(b0 + wm * 16 + g + rr * 8) * HH + jj];
    }

    // Reset flags for this warp's two fragment rows (mask + epilogue).
    const int fr0 = b0 + wm * 16 + g;
    bool f0 = resets[fr0] != 0, f1 = resets[fr0 + 8] != 0;

    float c[4][4];   // 0=r, 1=z, 2=xn, 3=hn

    // x-phase: fills c[0..2] with x_t @ W_i partials (own k-half). Depth-2 A prefetch.
#define X_PHASE(tx) {                                                              \
    _Pragma("unroll")                                                              \
    for (int i = 0; i < 3; ++i)                                                    \
        _Pragma("unroll")                                                          \
        for (int q = 0; q < 4; ++q) c[i][q] = 0.0f;                                \
    const size_t xb = (((size_t)(tx) * 16 + mtg) * 32 + wk * 16) * 32;             \
    uint4 fa0 = g_Xf[xb + l];                                                      \
    uint4 fa1 = g_Xf[xb + 32 + l];                                                 \
    _Pragma("unroll")                                                              \
    for (int ic = 0; ic < 16; ++ic) {                                              \
        uint4 nfa;                                                                 \
        if (ic < 14) nfa = g_Xf[xb + (ic + 2) * 32 + l];                           \
        const uint32_t af[4] = {fa0.x, fa0.y, fa0.z, fa0.w};                       \
        const uint32_t wb = smb + SKB_WI + (uint32_t)((wk * 16 + ic) * 1536) + woff_l; \
        _Pragma("unroll")                                                          \
        for (int gate = 0; gate < 3; ++gate) {                                     \
            uint32_t bf[4];                                                        \
            ldm_x4(bf, wb + (uint32_t)(gate * 512));                               \
            mma16816(c[gate], af, bf);        /* hi term */                        \
            mma16816(c[gate], af, bf + 2);    /* lo term */                        \
        }                                                                          \
        fa0 = fa1; fa1 = nfa;                                                      \
    } }

    X_PHASE(0);   // prologue

    for (int t = 0; t < TT; ++t) {
        const int par = t & 1;

        // ---- h-phase: h @ W_h into c[0..1] (+) and c[3] (fresh) ----
#pragma unroll
        for (int q = 0; q < 4; ++q) c[3][q] = 0.0f;
        {
            const uint32_t mm0 = f0 ? 0u : 0xFFFFFFFFu;
            const uint32_t mm1 = f1 ? 0u : 0xFFFFFFFFu;
            const size_t hb = (((size_t)par * 16 + mtg) * 32 + wk * 16) * 32;
            uint4 fa0 = g_Hf[hb + l];
            uint4 fa1 = g_Hf[hb + 32 + l];
#pragma unroll
            for (int ic = 0; ic < 16; ++ic) {
                uint4 nfa;
                if (ic < 14) nfa = g_Hf[hb + (ic + 2) * 32 + l];
                const uint32_t af[4] = {fa0.x & mm0, fa0.y & mm1, fa0.z & mm0, fa0.w & mm1};
                const uint32_t wb = smb + SKB_WH + (uint32_t)((wk * 16 + ic) * 1536) + woff_l;
#pragma unroll
                for (int gate = 0; gate < 3; ++gate) {
                    uint32_t bf[4];
                    ldm_x4(bf, wb + (uint32_t)(gate * 512));
                    float* acc = (gate < 2) ? c[gate] : c[3];
                    mma16816(acc, af, bf);
                    mma16816(acc, af, bf + 2);
                }
                fa0 = fa1; fa1 = nfa;
            }
        }

        // ---- 2-way k reduction: wk=1 writes 16 floats (8KB), wk=0 adds ----
        if (wk == 1) {
            float* dst = red_buf + wm * 32 + l;
#pragma unroll
            for (int i = 0; i < 4; ++i)
#pragma unroll
                for (int q = 0; q < 4; ++q)
                    dst[(i * 4 + q) * 128] = c[i][q];
        }
        __syncthreads();

        if (wk == 1) {
            // x-phase(t+1) overlaps wk=0's epilogue (x independent of h).
            if (t + 1 < TT) {
                f0 = resets[(t + 1) * BB + fr0] != 0;
                f1 = resets[(t + 1) * BB + fr0 + 8] != 0;
                X_PHASE(t + 1);
            }
        } else {
            const float* src = red_buf + wm * 32 + l;
#pragma unroll
            for (int i = 0; i < 4; ++i)
#pragma unroll
                for (int q = 0; q < 4; ++q)
                    c[i][q] += src[(i * 4 + q) * 128];

            // ---- fused GRU epilogue: 2 rows x 2 cols; carry in registers ----
            float* outt = out + (size_t)t * BB * HH;
            uint32_t ph[2];
#pragma unroll
            for (int rr = 0; rr < 2; ++rr) {
                const int row = b0 + wm * 16 + g + rr * 8;
                const bool rz = (rr == 0) ? f0 : f1;
                float2 hp = hc[rr];
                if (rz) { hp.x = 0.0f; hp.y = 0.0f; }
                const float r0 = sigmoidf_(c[0][rr * 2 + 0] + bir2.x);
                const float r1 = sigmoidf_(c[0][rr * 2 + 1] + bir2.y);
                const float z0 = sigmoidf_(c[1][rr * 2 + 0] + biz2.x);
                const float z1 = sigmoidf_(c[1][rr * 2 + 1] + biz2.y);
                const float n0 = tanhf(c[2][rr * 2 + 0] + bin2.x + r0 * (c[3][rr * 2 + 0] + bhn2.x));
                const float n1 = tanhf(c[2][rr * 2 + 1] + bin2.y + r1 * (c[3][rr * 2 + 1] + bhn2.y));
                const float h0 = (1.0f - z0) * n0 + z0 * hp.x;
                const float h1 = (1.0f - z1) * n1 + z1 * hp.y;
                *(float2*)&outt[(size_t)row * HH + jj] = make_float2(h0, h1);
                hc[rr] = make_float2(h0, h1);
                ph[rr] = (uint32_t)h16(h0) | ((uint32_t)h16(h1) << 16);
            }
            // h fragment store: uint2 half (jpar) of the a-frag uint4 at
            // (parity^1, mtg, kbj, lane l).
            const size_t widx = (((size_t)(par ^ 1) * 16 + mtg) * 32 + kbj) * 32 + l;
            ((uint2*)&g_Hf[widx])[jpar] = make_uint2(ph[0], ph[1]);
        }

        if (t + 1 < TT) {
            __syncthreads();   // h stores done before the release-arrive
            if (tid == 0)
                asm volatile("red.release.gpu.add.u32 [%0], %1;" :: "l"(my_bar), "r"(1u) : "memory");

            if (wk == 0) {     // wk=1 already did its x-phase during the epilogue
                f0 = resets[(t + 1) * BB + fr0] != 0;
                f1 = resets[(t + 1) * BB + fr0 + 8] != 0;
                X_PHASE(t + 1);
            }

            if (tid == 0) {
                const unsigned target = 64u * (unsigned)(t + 1);
                unsigned v;
                do {
                    asm volatile("ld.acquire.gpu.u32 %0, [%1];" : "=r"(v) : "l"(my_bar) : "memory");
                    if (v >= target) break;
                    __nanosleep(32);
                } while (true);
            }
            __syncthreads();
        }
    }
#undef X_PHASE
}

// ----------------------------------------------------------------------------
// Launch: 3 prep kernels + ONE fused fragment-fed persistent kernel.
// Graph-capturable (kernel launches only), allocation-free.
// ----------------------------------------------------------------------------
extern "C" void kernel_launch(void* const* d_in, const int* in_sizes, int n_in,
                              void* d_out, int out_size)
{
    const float* ins    = (const float*)d_in[0];
    const int*   resets = (const int*)d_in[1];
    const float* init_h = (const float*)d_in[2];
    const float* W_ir   = (const float*)d_in[3];
    const float* W_iz   = (const float*)d_in[4];
    const float* W_in   = (const float*)d_in[5];
    const float* b_ir   = (const float*)d_in[6];
    const float* b_iz   = (const float*)d_in[7];
    const float* b_in   = (const float*)d_in[8];
    const float* W_hr   = (const float*)d_in[9];
    const float* W_hz   = (const float*)d_in[10];
    const float* W_hn   = (const float*)d_in[11];
    const float* b_hn   = (const float*)d_in[12];
    float* out = (float*)d_out;

    cudaFuncSetAttribute(gru_persistent,
                         cudaFuncAttributeMaxDynamicSharedMemorySize, SKB_TOTAL);

    prep_x_kernel<<<(int)(((size_t)TT * 16 * 32 * 32 + 255) / 256), 256>>>(ins);
    prep_w_kernel<<<(G3 * HH / 8 + 255) / 256, 256>>>(W_ir, W_iz, W_in,
                                                      W_hr, W_hz, W_hn,
                                                      b_ir, b_iz, b_in);
    prep_h_kernel<<<(16 * 32 * 32 + 255) / 256, 256>>>(init_h);

    gru_persistent<<<dim3(64, 4), 256, SKB_TOTAL>>>(resets, init_h, b_hn, out);
}